// round 12
// baseline (speedup 1.0000x reference)
#include <cuda_runtime.h>
#include <cuda_bf16.h>
#include <cstdint>

#define B_    4
#define CIN_  256
#define P_    4096
#define K_    9
#define RDIM  2304          // CIN*9
#define COUT_ 256
#define NTOT  16384         // B*P

// ---------------------------------------------------------------------------
// Device scratch (static — no cudaMalloc allowed)
// ---------------------------------------------------------------------------
__device__ __align__(128) __nv_bfloat16 g_hi[(size_t)RDIM * NTOT];
__device__ __align__(128) __nv_bfloat16 g_lo[(size_t)RDIM * NTOT];
__device__ __align__(128) __nv_bfloat16 g_whi[COUT_ * RDIM];
__device__ __align__(128) __nv_bfloat16 g_wlo[COUT_ * RDIM];

__device__ __forceinline__ uint32_t smem_u32(const void* p) {
    uint32_t a;
    asm("{ .reg .u64 t; cvta.to.shared.u64 t, %1; cvt.u32.u64 %0, t; }"
        : "=r"(a) : "l"(p));
    return a;
}

#define CP16(dst, src) \
    asm volatile("cp.async.cg.shared.global [%0], [%1], 16;" \
                 :: "r"(dst), "l"(src) : "memory")
#define CP_COMMIT() asm volatile("cp.async.commit_group;" ::: "memory")
#define CP_WAIT1()  asm volatile("cp.async.wait_group 1;" ::: "memory")
#define CP_WAIT0()  asm volatile("cp.async.wait_group 0;" ::: "memory")

#define LDMX4(r0, r1, r2, r3, a) \
    asm volatile("ldmatrix.sync.aligned.m8n8.x4.shared.b16 {%0,%1,%2,%3}, [%4];" \
                 : "=r"(r0), "=r"(r1), "=r"(r2), "=r"(r3) : "r"(a))
#define LDMX4T(r0, r1, r2, r3, a) \
    asm volatile("ldmatrix.sync.aligned.m8n8.x4.trans.shared.b16 {%0,%1,%2,%3}, [%4];" \
                 : "=r"(r0), "=r"(r1), "=r"(r2), "=r"(r3) : "r"(a))

#define MMA16816(d, a, b0, b1) \
    asm volatile("mma.sync.aligned.m16n8k16.row.col.f32.bf16.bf16.f32 " \
                 "{%0,%1,%2,%3},{%4,%5,%6,%7},{%8,%9},{%0,%1,%2,%3};" \
                 : "+f"((d)[0]), "+f"((d)[1]), "+f"((d)[2]), "+f"((d)[3]) \
                 : "r"((a)[0]), "r"((a)[1]), "r"((a)[2]), "r"((a)[3]), \
                   "r"(b0), "r"(b1))

__device__ __forceinline__ uint32_t pk_bf2(__nv_bfloat16 a, __nv_bfloat16 b) {
    return (uint32_t)__bfloat16_as_ushort(a) |
           ((uint32_t)__bfloat16_as_ushort(b) << 16);
}

// ---------------------------------------------------------------------------
// Kernel 1: weight split (folded) + fused sampling + im2col -> bf16 hi/lo
//   2 p's per thread, channel loop split across 2 blocks.
//   grid (16, 9, 4) = 576 blocks x 256 threads.
// ---------------------------------------------------------------------------
__global__ __launch_bounds__(256) void im2col_kernel(
    const float* __restrict__ x,
    const float* __restrict__ offset,
    const float* __restrict__ mask,
    const float* __restrict__ weight)
{
    const int tid = threadIdx.x;
    const int k = blockIdx.y, b = blockIdx.z;
    const int pxb = blockIdx.x >> 1;
    const int chalf = blockIdx.x & 1;
    const int p0 = pxb * 512 + tid * 2;

    // ---- folded weight split: 589824 = 4 * 147456 threads
    {
        int flat = (((b * 9 + k) << 4) + blockIdx.x) * 256 + tid;
        #pragma unroll
        for (int j = 0; j < 4; j++) {
            int i = flat + j * 147456;
            float v = weight[i];
            __nv_bfloat16 h = __float2bfloat16(v);
            g_whi[i] = h;
            g_wlo[i] = __float2bfloat16(v - __bfloat162float(h));
        }
    }

    const int kh = k / 3, kw = k - kh * 3;
    const float* offb = offset + (b * 18 + 2 * k) * P_;
    const float* mb   = mask + (b * 9 + k) * P_;

    int   idx[2][4];
    float wgt[2][4];
    #pragma unroll
    for (int pi = 0; pi < 2; pi++) {
        int p = p0 + pi;
        int oy = p >> 6, ox = p & 63;
        float dy = offb[p];
        float dx = offb[P_ + p];
        float m  = mb[p];

        float sy = (float)(oy - 1 + kh) + dy;
        float sx = (float)(ox - 1 + kw) + dx;
        float y0f = floorf(sy), x0f = floorf(sx);
        float wy = sy - y0f,    wx = sx - x0f;
        int y0 = (int)y0f, x0 = (int)x0f;
        int y1 = y0 + 1,   x1 = x0 + 1;

        bool vy0 = ((unsigned)y0 < 64u), vy1 = ((unsigned)y1 < 64u);
        bool vx0 = ((unsigned)x0 < 64u), vx1 = ((unsigned)x1 < 64u);
        int cy0 = min(max(y0, 0), 63), cy1 = min(max(y1, 0), 63);
        int cx0 = min(max(x0, 0), 63), cx1 = min(max(x1, 0), 63);
        idx[pi][0] = cy0 * 64 + cx0; idx[pi][1] = cy0 * 64 + cx1;
        idx[pi][2] = cy1 * 64 + cx0; idx[pi][3] = cy1 * 64 + cx1;

        float w00 = (1.f - wy) * (1.f - wx) * m; if (!(vy0 && vx0)) w00 = 0.f;
        float w01 = (1.f - wy) * wx * m;         if (!(vy0 && vx1)) w01 = 0.f;
        float w10 = wy * (1.f - wx) * m;         if (!(vy1 && vx0)) w10 = 0.f;
        float w11 = wy * wx * m;                 if (!(vy1 && vx1)) w11 = 0.f;
        wgt[pi][0] = w00; wgt[pi][1] = w01; wgt[pi][2] = w10; wgt[pi][3] = w11;
    }

    const int c0 = chalf * 128;
    const float* xb = x + b * (CIN_ * P_) + c0 * P_;
    const size_t nbase = (size_t)b * P_ + p0;

    #pragma unroll 2
    for (int ci = 0; ci < 128; ci++) {
        const float* xp = xb + ci * P_;
        float v0 = wgt[0][0] * __ldg(xp + idx[0][0])
                 + wgt[0][1] * __ldg(xp + idx[0][1])
                 + wgt[0][2] * __ldg(xp + idx[0][2])
                 + wgt[0][3] * __ldg(xp + idx[0][3]);
        float v1 = wgt[1][0] * __ldg(xp + idx[1][0])
                 + wgt[1][1] * __ldg(xp + idx[1][1])
                 + wgt[1][2] * __ldg(xp + idx[1][2])
                 + wgt[1][3] * __ldg(xp + idx[1][3]);
        __nv_bfloat16 h0 = __float2bfloat16(v0);
        __nv_bfloat16 h1 = __float2bfloat16(v1);
        __nv_bfloat16 l0 = __float2bfloat16(v0 - __bfloat162float(h0));
        __nv_bfloat16 l1 = __float2bfloat16(v1 - __bfloat162float(h1));
        size_t off = (size_t)((c0 + ci) * 9 + k) * NTOT + nbase;
        *(uint32_t*)(g_hi + off) = pk_bf2(h0, h1);
        *(uint32_t*)(g_lo + off) = pk_bf2(l0, l1);
    }
}

// ---------------------------------------------------------------------------
// Kernel 2: bf16 split-precision GEMM via mma.sync (HMMA)
//   CTA tile 64x128, K-chunk 64, 8 warps (2x4), warp tile 32x32,
//   2-stage double buffer, 2 CTAs per SM (independent barrier phases).
// ---------------------------------------------------------------------------
#define BK      64
#define NCH     (RDIM / BK)       // 36
#define A_STRIDE 144              // bytes per m-row (128 data + 16 pad)
#define B_STRIDE 272              // bytes per k-row (256 data + 16 pad)
#define OFF_AH  0
#define OFF_AL  (64 * A_STRIDE)               // 9216
#define OFF_BH  (2 * 64 * A_STRIDE)           // 18432
#define OFF_BL  (OFF_BH + 64 * B_STRIDE)      // 35840
#define STAGE_BYTES (OFF_BL + 64 * B_STRIDE)  // 53248
#define SMEM_TOTAL (2 * STAGE_BYTES)          // 106496

__global__ __launch_bounds__(256, 2) void gemm_mma_kernel(
    const float* __restrict__ bias, float* __restrict__ out)
{
    extern __shared__ char smem[];
    const uint32_t sb0 = smem_u32(smem);
    const int tid = threadIdx.x;
    const int lane = tid & 31, wid = tid >> 5;
    const int warp_m = wid >> 2;          // 0..1  -> m offset *32
    const int warp_n = wid & 3;           // 0..3  -> n offset *32
    const int bm = blockIdx.y * 64;
    const int n0 = blockIdx.x * 128;

    const int lgrp = lane >> 3, lr = lane & 7;
    const int a_row   = ((lgrp & 1) << 3) + lr;
    const int a_chunk = lgrp >> 1;
    const int b_krow  = ((lgrp & 1) << 3) + lr;
    const int b_col   = (warp_n << 5) + ((lgrp >> 1) << 3);

    const __nv_bfloat16* WH = g_whi + (size_t)bm * RDIM;
    const __nv_bfloat16* WL = g_wlo + (size_t)bm * RDIM;

    // cp.async indexing (256 threads)
    const int a_r = tid >> 2, a_h = tid & 3;   // A: 64 rows, 8x16B per row
    const int b_r = tid >> 4, b_c = tid & 15;  // B: 64 rows, 16x16B per row

    float d[2][4][4];
    #pragma unroll
    for (int i = 0; i < 2; i++)
        #pragma unroll
        for (int j = 0; j < 4; j++)
            #pragma unroll
            for (int q = 0; q < 4; q++) d[i][j][q] = 0.f;

    auto load_stage = [&](int ch) {
        const int kc0 = ch * BK;
        const uint32_t st = sb0 + (ch & 1) * STAGE_BYTES;
        #pragma unroll
        for (int q = 0; q < 2; q++) {
            int c16 = a_h + q * 4;
            uint32_t dsta = st + OFF_AH + a_r * A_STRIDE + c16 * 16;
            size_t go = (size_t)a_r * RDIM + kc0 + c16 * 8;
            CP16(dsta, WH + go);
            CP16(dsta + (OFF_AL - OFF_AH), WL + go);
        }
        #pragma unroll
        for (int q = 0; q < 4; q++) {
            int r = b_r + q * 16;
            uint32_t dstb = st + OFF_BH + r * B_STRIDE + b_c * 16;
            size_t go = (size_t)(kc0 + r) * NTOT + n0 + b_c * 8;
            CP16(dstb, g_hi + go);
            CP16(dstb + (OFF_BL - OFF_BH), g_lo + go);
        }
    };

    load_stage(0); CP_COMMIT();

    for (int ch = 0; ch < NCH; ch++) {
        if (ch + 1 < NCH) {
            load_stage(ch + 1); CP_COMMIT();
            CP_WAIT1();
        } else {
            CP_WAIT0();
        }
        __syncthreads();

        const uint32_t st = sb0 + (ch & 1) * STAGE_BYTES;
        const uint32_t aHbase = st + OFF_AH +
            (warp_m * 32 + a_row) * A_STRIDE + a_chunk * 16;
        const uint32_t bHbase = st + OFF_BH + b_krow * B_STRIDE + b_col * 2;

        #pragma unroll
        for (int s = 0; s < 4; s++) {
            uint32_t afh[2][4], afl[2][4], bfh[2][4], bfl[2][4];
            #pragma unroll
            for (int i = 0; i < 2; i++) {
                uint32_t aa = aHbase + i * (16 * A_STRIDE) + s * 32;
                LDMX4(afh[i][0], afh[i][1], afh[i][2], afh[i][3], aa);
                LDMX4(afl[i][0], afl[i][1], afl[i][2], afl[i][3],
                      aa + (OFF_AL - OFF_AH));
            }
            #pragma unroll
            for (int g = 0; g < 2; g++) {
                uint32_t ba = bHbase + s * (16 * B_STRIDE) + g * 32;
                LDMX4T(bfh[g][0], bfh[g][1], bfh[g][2], bfh[g][3], ba);
                LDMX4T(bfl[g][0], bfl[g][1], bfl[g][2], bfl[g][3],
                       ba + (OFF_BL - OFF_BH));
            }
            #pragma unroll
            for (int i = 0; i < 2; i++)
                #pragma unroll
                for (int g = 0; g < 2; g++)
                    #pragma unroll
                    for (int jn = 0; jn < 2; jn++)
                        MMA16816(d[i][g * 2 + jn], afh[i],
                                 bfh[g][jn * 2], bfh[g][jn * 2 + 1]);
            #pragma unroll
            for (int i = 0; i < 2; i++)
                #pragma unroll
                for (int g = 0; g < 2; g++)
                    #pragma unroll
                    for (int jn = 0; jn < 2; jn++)
                        MMA16816(d[i][g * 2 + jn], afh[i],
                                 bfl[g][jn * 2], bfl[g][jn * 2 + 1]);
            #pragma unroll
            for (int i = 0; i < 2; i++)
                #pragma unroll
                for (int g = 0; g < 2; g++)
                    #pragma unroll
                    for (int jn = 0; jn < 2; jn++)
                        MMA16816(d[i][g * 2 + jn], afl[i],
                                 bfh[g][jn * 2], bfh[g][jn * 2 + 1]);
        }
        __syncthreads();   // all reads of this buffer done before it is refilled
    }

    // ---- epilogue ----
    const int row0 = lane >> 2, col0 = (lane & 3) * 2;
    const int bb = n0 >> 12;
    const int pbase = (n0 & 4095) + warp_n * 32 + col0;
    #pragma unroll
    for (int i = 0; i < 2; i++) {
        int co = bm + warp_m * 32 + i * 16 + row0;
        float bi0 = __ldg(bias + co);
        float bi1 = __ldg(bias + co + 8);
        float* o0 = out + ((size_t)(bb * COUT_ + co)) * P_ + pbase;
        float* o1 = o0 + 8 * P_;
        #pragma unroll
        for (int j = 0; j < 4; j++) {
            float2 v0 = make_float2(d[i][j][0] + bi0, d[i][j][1] + bi0);
            float2 v1 = make_float2(d[i][j][2] + bi1, d[i][j][3] + bi1);
            *(float2*)(o0 + j * 8) = v0;
            *(float2*)(o1 + j * 8) = v1;
        }
    }
}

// ---------------------------------------------------------------------------
extern "C" void kernel_launch(void* const* d_in, const int* in_sizes, int n_in,
                              void* d_out, int out_size) {
    const float* x      = (const float*)d_in[0];
    const float* offset = (const float*)d_in[1];
    const float* mask   = (const float*)d_in[2];
    const float* weight = (const float*)d_in[3];
    const float* bias   = (const float*)d_in[4];
    float* out = (float*)d_out;

    cudaFuncSetAttribute(gemm_mma_kernel,
                         cudaFuncAttributeMaxDynamicSharedMemorySize, SMEM_TOTAL);

    im2col_kernel<<<dim3(16, K_, B_), 256>>>(x, offset, mask, weight);
    gemm_mma_kernel<<<dim3(NTOT / 128, COUT_ / 64), 256, SMEM_TOTAL>>>(bias, out);
}

// round 13
// speedup vs baseline: 1.2995x; 1.2995x over previous
#include <cuda_runtime.h>
#include <cuda_fp16.h>
#include <cstdint>

#define B_    4
#define CIN_  256
#define P_    4096
#define K_    9
#define RDIM  2304          // CIN*9
#define COUT_ 256
#define NTOT  16384         // B*P

#define LO_SCALE 2048.0f
#define LO_INV   (1.0f / 2048.0f)

// ---------------------------------------------------------------------------
// Device scratch (static — no cudaMalloc allowed)
// ---------------------------------------------------------------------------
__device__ __align__(128) __half g_cols[(size_t)RDIM * NTOT];  // fp16 cols [r][n]
__device__ __align__(128) __half g_whi[COUT_ * RDIM];
__device__ __align__(128) __half g_wlo[COUT_ * RDIM];          // residual * 2048

__device__ __forceinline__ uint32_t smem_u32(const void* p) {
    uint32_t a;
    asm("{ .reg .u64 t; cvta.to.shared.u64 t, %1; cvt.u32.u64 %0, t; }"
        : "=r"(a) : "l"(p));
    return a;
}

#define CP16(dst, src) \
    asm volatile("cp.async.cg.shared.global [%0], [%1], 16;" \
                 :: "r"(dst), "l"(src) : "memory")
#define CP_COMMIT() asm volatile("cp.async.commit_group;" ::: "memory")
#define CP_WAIT1()  asm volatile("cp.async.wait_group 1;" ::: "memory")

#define LDMX4(r0, r1, r2, r3, a) \
    asm volatile("ldmatrix.sync.aligned.m8n8.x4.shared.b16 {%0,%1,%2,%3}, [%4];" \
                 : "=r"(r0), "=r"(r1), "=r"(r2), "=r"(r3) : "r"(a))
#define LDMX4T(r0, r1, r2, r3, a) \
    asm volatile("ldmatrix.sync.aligned.m8n8.x4.trans.shared.b16 {%0,%1,%2,%3}, [%4];" \
                 : "=r"(r0), "=r"(r1), "=r"(r2), "=r"(r3) : "r"(a))

#define MMA16816F(d, a, b0, b1) \
    asm volatile("mma.sync.aligned.m16n8k16.row.col.f32.f16.f16.f32 " \
                 "{%0,%1,%2,%3},{%4,%5,%6,%7},{%8,%9},{%0,%1,%2,%3};" \
                 : "+f"((d)[0]), "+f"((d)[1]), "+f"((d)[2]), "+f"((d)[3]) \
                 : "r"((a)[0]), "r"((a)[1]), "r"((a)[2]), "r"((a)[3]), \
                   "r"(b0), "r"(b1))

__device__ __forceinline__ uint32_t pk_h2(__half a, __half b) {
    return (uint32_t)__half_as_ushort(a) | ((uint32_t)__half_as_ushort(b) << 16);
}

// ---------------------------------------------------------------------------
// Kernel 1: weight split (folded, scaled residual) + im2col -> fp16 cols
//   2 p's per thread, channel loop split across 2 blocks.
//   grid (16, 9, 4) = 576 blocks x 256 threads.
// ---------------------------------------------------------------------------
__global__ __launch_bounds__(256) void im2col_kernel(
    const float* __restrict__ x,
    const float* __restrict__ offset,
    const float* __restrict__ mask,
    const float* __restrict__ weight)
{
    const int tid = threadIdx.x;
    const int k = blockIdx.y, b = blockIdx.z;
    const int pxb = blockIdx.x >> 1;
    const int chalf = blockIdx.x & 1;
    const int p0 = pxb * 512 + tid * 2;

    // ---- folded weight split: 589824 = 4 * 147456 threads
    {
        int flat = (((b * 9 + k) << 4) + blockIdx.x) * 256 + tid;
        #pragma unroll
        for (int j = 0; j < 4; j++) {
            int i = flat + j * 147456;
            float v = weight[i];
            __half h = __float2half_rn(v);
            g_whi[i] = h;
            g_wlo[i] = __float2half_rn((v - __half2float(h)) * LO_SCALE);
        }
    }

    const int kh = k / 3, kw = k - kh * 3;
    const float* offb = offset + (b * 18 + 2 * k) * P_;
    const float* mb   = mask + (b * 9 + k) * P_;

    int   idx[2][4];
    float wgt[2][4];
    #pragma unroll
    for (int pi = 0; pi < 2; pi++) {
        int p = p0 + pi;
        int oy = p >> 6, ox = p & 63;
        float dy = offb[p];
        float dx = offb[P_ + p];
        float m  = mb[p];

        float sy = (float)(oy - 1 + kh) + dy;
        float sx = (float)(ox - 1 + kw) + dx;
        float y0f = floorf(sy), x0f = floorf(sx);
        float wy = sy - y0f,    wx = sx - x0f;
        int y0 = (int)y0f, x0 = (int)x0f;
        int y1 = y0 + 1,   x1 = x0 + 1;

        bool vy0 = ((unsigned)y0 < 64u), vy1 = ((unsigned)y1 < 64u);
        bool vx0 = ((unsigned)x0 < 64u), vx1 = ((unsigned)x1 < 64u);
        int cy0 = min(max(y0, 0), 63), cy1 = min(max(y1, 0), 63);
        int cx0 = min(max(x0, 0), 63), cx1 = min(max(x1, 0), 63);
        idx[pi][0] = cy0 * 64 + cx0; idx[pi][1] = cy0 * 64 + cx1;
        idx[pi][2] = cy1 * 64 + cx0; idx[pi][3] = cy1 * 64 + cx1;

        float w00 = (1.f - wy) * (1.f - wx) * m; if (!(vy0 && vx0)) w00 = 0.f;
        float w01 = (1.f - wy) * wx * m;         if (!(vy0 && vx1)) w01 = 0.f;
        float w10 = wy * (1.f - wx) * m;         if (!(vy1 && vx0)) w10 = 0.f;
        float w11 = wy * wx * m;                 if (!(vy1 && vx1)) w11 = 0.f;
        wgt[pi][0] = w00; wgt[pi][1] = w01; wgt[pi][2] = w10; wgt[pi][3] = w11;
    }

    const int c0 = chalf * 128;
    const float* xb = x + b * (CIN_ * P_) + c0 * P_;
    const size_t nbase = (size_t)b * P_ + p0;

    #pragma unroll 2
    for (int ci = 0; ci < 128; ci++) {
        const float* xp = xb + ci * P_;
        float v0 = wgt[0][0] * __ldg(xp + idx[0][0])
                 + wgt[0][1] * __ldg(xp + idx[0][1])
                 + wgt[0][2] * __ldg(xp + idx[0][2])
                 + wgt[0][3] * __ldg(xp + idx[0][3]);
        float v1 = wgt[1][0] * __ldg(xp + idx[1][0])
                 + wgt[1][1] * __ldg(xp + idx[1][1])
                 + wgt[1][2] * __ldg(xp + idx[1][2])
                 + wgt[1][3] * __ldg(xp + idx[1][3]);
        size_t off = (size_t)((c0 + ci) * 9 + k) * NTOT + nbase;
        *(uint32_t*)(g_cols + off) =
            pk_h2(__float2half_rn(v0), __float2half_rn(v1));
    }
}

// ---------------------------------------------------------------------------
// Kernel 2: fp16 2-product GEMM via mma.sync (HMMA), scaled residual
//   C = Wh*B (accH) ; Wl*B (accL) ; out = accH + accL/2048 + bias
//   CTA 128x128, K-chunk 64, 16 warps (4x4), warp tile 32x32, 3-stage cp.async
// ---------------------------------------------------------------------------
#define BK      64
#define NCH     (RDIM / BK)       // 36
#define A_STRIDE 144              // bytes per m-row (128 data + 16 pad)
#define B_STRIDE 272              // bytes per k-row (256 data + 16 pad)
#define OFF_AH  0
#define OFF_AL  (128 * A_STRIDE)              // 18432
#define OFF_B   (2 * 128 * A_STRIDE)          // 36864
#define STAGE_BYTES (OFF_B + 64 * B_STRIDE)   // 54272
#define SMEM_TOTAL (3 * STAGE_BYTES)          // 162816

__global__ __launch_bounds__(512, 1) void gemm_mma_kernel(
    const float* __restrict__ bias, float* __restrict__ out)
{
    extern __shared__ char smem[];
    const uint32_t sb0 = smem_u32(smem);
    const int tid = threadIdx.x;
    const int lane = tid & 31, wid = tid >> 5;
    const int warp_m = wid >> 2;          // 0..3  -> m offset *32
    const int warp_n = wid & 3;           // 0..3  -> n offset *32
    const int bm = blockIdx.y * 128;
    const int n0 = blockIdx.x * 128;

    const int lgrp = lane >> 3, lr = lane & 7;
    const int a_row   = ((lgrp & 1) << 3) + lr;
    const int a_chunk = lgrp >> 1;
    const int b_krow  = ((lgrp & 1) << 3) + lr;
    const int b_col   = (warp_n << 5) + ((lgrp >> 1) << 3);

    const __half* WH = g_whi + (size_t)bm * RDIM;
    const __half* WL = g_wlo + (size_t)bm * RDIM;

    const int a_r = tid >> 2, a_h = tid & 3;   // A: 128 rows, 8x16B per row
    const int b_r = tid >> 3, b_c = tid & 7;   // B: 64 rows, 16x16B per row

    float dH[2][4][4], dL[2][4][4];
    #pragma unroll
    for (int i = 0; i < 2; i++)
        #pragma unroll
        for (int j = 0; j < 4; j++)
            #pragma unroll
            for (int q = 0; q < 4; q++) { dH[i][j][q] = 0.f; dL[i][j][q] = 0.f; }

    auto load_stage = [&](int ch) {
        const int kc0 = ch * BK;
        const uint32_t st = sb0 + (ch % 3) * STAGE_BYTES;
        #pragma unroll
        for (int q = 0; q < 2; q++) {
            int c16 = a_h + q * 4;
            uint32_t dsta = st + OFF_AH + a_r * A_STRIDE + c16 * 16;
            size_t go = (size_t)a_r * RDIM + kc0 + c16 * 8;
            CP16(dsta, WH + go);
            CP16(dsta + (OFF_AL - OFF_AH), WL + go);
        }
        #pragma unroll
        for (int q = 0; q < 2; q++) {
            int c16 = b_c + q * 8;
            uint32_t dstb = st + OFF_B + b_r * B_STRIDE + c16 * 16;
            CP16(dstb, g_cols + (size_t)(kc0 + b_r) * NTOT + n0 + c16 * 8);
        }
    };

    load_stage(0); CP_COMMIT();
    load_stage(1); CP_COMMIT();

    for (int ch = 0; ch < NCH; ch++) {
        CP_WAIT1();
        __syncthreads();
        if (ch + 2 < NCH) load_stage(ch + 2);
        CP_COMMIT();

        const uint32_t st = sb0 + (ch % 3) * STAGE_BYTES;
        const uint32_t aHbase = st + OFF_AH +
            (warp_m * 32 + a_row) * A_STRIDE + a_chunk * 16;
        const uint32_t bBase = st + OFF_B + b_krow * B_STRIDE + b_col * 2;

        #pragma unroll
        for (int s = 0; s < 4; s++) {
            uint32_t afh[2][4], afl[2][4], bf[2][4];
            #pragma unroll
            for (int i = 0; i < 2; i++) {
                uint32_t aa = aHbase + i * (16 * A_STRIDE) + s * 32;
                LDMX4(afh[i][0], afh[i][1], afh[i][2], afh[i][3], aa);
                LDMX4(afl[i][0], afl[i][1], afl[i][2], afl[i][3],
                      aa + (OFF_AL - OFF_AH));
            }
            #pragma unroll
            for (int g = 0; g < 2; g++) {
                uint32_t ba = bBase + s * (16 * B_STRIDE) + g * 32;
                LDMX4T(bf[g][0], bf[g][1], bf[g][2], bf[g][3], ba);
            }
            // hi product -> accH  (8 MMAs, distinct accumulators)
            #pragma unroll
            for (int i = 0; i < 2; i++)
                #pragma unroll
                for (int g = 0; g < 2; g++)
                    #pragma unroll
                    for (int jn = 0; jn < 2; jn++)
                        MMA16816F(dH[i][g * 2 + jn], afh[i],
                                  bf[g][jn * 2], bf[g][jn * 2 + 1]);
            // lo (scaled) product -> accL
            #pragma unroll
            for (int i = 0; i < 2; i++)
                #pragma unroll
                for (int g = 0; g < 2; g++)
                    #pragma unroll
                    for (int jn = 0; jn < 2; jn++)
                        MMA16816F(dL[i][g * 2 + jn], afl[i],
                                  bf[g][jn * 2], bf[g][jn * 2 + 1]);
        }
    }

    // ---- epilogue: out = accH + accL/2048 + bias ----
    const int row0 = lane >> 2, col0 = (lane & 3) * 2;
    const int bb = n0 >> 12;
    const int pbase = (n0 & 4095) + warp_n * 32 + col0;
    #pragma unroll
    for (int i = 0; i < 2; i++) {
        int co = bm + warp_m * 32 + i * 16 + row0;
        float bi0 = __ldg(bias + co);
        float bi1 = __ldg(bias + co + 8);
        float* o0 = out + ((size_t)(bb * COUT_ + co)) * P_ + pbase;
        float* o1 = o0 + 8 * P_;
        #pragma unroll
        for (int j = 0; j < 4; j++) {
            float2 v0 = make_float2(dH[i][j][0] + dL[i][j][0] * LO_INV + bi0,
                                    dH[i][j][1] + dL[i][j][1] * LO_INV + bi0);
            float2 v1 = make_float2(dH[i][j][2] + dL[i][j][2] * LO_INV + bi1,
                                    dH[i][j][3] + dL[i][j][3] * LO_INV + bi1);
            *(float2*)(o0 + j * 8) = v0;
            *(float2*)(o1 + j * 8) = v1;
        }
    }
}

// ---------------------------------------------------------------------------
extern "C" void kernel_launch(void* const* d_in, const int* in_sizes, int n_in,
                              void* d_out, int out_size) {
    const float* x      = (const float*)d_in[0];
    const float* offset = (const float*)d_in[1];
    const float* mask   = (const float*)d_in[2];
    const float* weight = (const float*)d_in[3];
    const float* bias   = (const float*)d_in[4];
    float* out = (float*)d_out;

    cudaFuncSetAttribute(gemm_mma_kernel,
                         cudaFuncAttributeMaxDynamicSharedMemorySize, SMEM_TOTAL);

    im2col_kernel<<<dim3(16, K_, B_), 256>>>(x, offset, mask, weight);
    gemm_mma_kernel<<<dim3(NTOT / 128, COUT_ / 128), 512, SMEM_TOTAL>>>(bias, out);
}

// round 14
// speedup vs baseline: 1.7167x; 1.3211x over previous
#include <cuda_runtime.h>
#include <cuda_fp16.h>
#include <cstdint>

#define B_    4
#define CIN_  256
#define P_    4096
#define K_    9
#define RDIM  2304          // CIN*9
#define COUT_ 256
#define NTOT  16384         // B*P

// ---------------------------------------------------------------------------
// Device scratch (static — no cudaMalloc allowed)
// ---------------------------------------------------------------------------
__device__ __align__(128) __half g_cols[(size_t)RDIM * NTOT];  // fp16 cols [r][n]
__device__ __align__(128) __half g_wh[COUT_ * RDIM];           // fp16 weights

__device__ __forceinline__ uint32_t smem_u32(const void* p) {
    uint32_t a;
    asm("{ .reg .u64 t; cvta.to.shared.u64 t, %1; cvt.u32.u64 %0, t; }"
        : "=r"(a) : "l"(p));
    return a;
}

#define CP16(dst, src) \
    asm volatile("cp.async.cg.shared.global [%0], [%1], 16;" \
                 :: "r"(dst), "l"(src) : "memory")
#define CP_COMMIT() asm volatile("cp.async.commit_group;" ::: "memory")
#define CP_WAIT2()  asm volatile("cp.async.wait_group 2;" ::: "memory")

#define LDMX4(r0, r1, r2, r3, a) \
    asm volatile("ldmatrix.sync.aligned.m8n8.x4.shared.b16 {%0,%1,%2,%3}, [%4];" \
                 : "=r"(r0), "=r"(r1), "=r"(r2), "=r"(r3) : "r"(a))
#define LDMX4T(r0, r1, r2, r3, a) \
    asm volatile("ldmatrix.sync.aligned.m8n8.x4.trans.shared.b16 {%0,%1,%2,%3}, [%4];" \
                 : "=r"(r0), "=r"(r1), "=r"(r2), "=r"(r3) : "r"(a))

#define MMA16816F(d, a, b0, b1) \
    asm volatile("mma.sync.aligned.m16n8k16.row.col.f32.f16.f16.f32 " \
                 "{%0,%1,%2,%3},{%4,%5,%6,%7},{%8,%9},{%0,%1,%2,%3};" \
                 : "+f"((d)[0]), "+f"((d)[1]), "+f"((d)[2]), "+f"((d)[3]) \
                 : "r"((a)[0]), "r"((a)[1]), "r"((a)[2]), "r"((a)[3]), \
                   "r"(b0), "r"(b1))

__device__ __forceinline__ uint32_t pk_h2(__half a, __half b) {
    return (uint32_t)__half_as_ushort(a) | ((uint32_t)__half_as_ushort(b) << 16);
}

// ---------------------------------------------------------------------------
// Kernel 1: weight fp16 convert (folded) + fused sampling + im2col -> fp16
//   2 p's per thread, channel loop split across 2 blocks.
//   grid (16, 9, 4) = 576 blocks x 256 threads.
// ---------------------------------------------------------------------------
__global__ __launch_bounds__(256) void im2col_kernel(
    const float* __restrict__ x,
    const float* __restrict__ offset,
    const float* __restrict__ mask,
    const float* __restrict__ weight)
{
    const int tid = threadIdx.x;
    const int k = blockIdx.y, b = blockIdx.z;
    const int pxb = blockIdx.x >> 1;
    const int chalf = blockIdx.x & 1;
    const int p0 = pxb * 512 + tid * 2;

    // ---- folded weight convert: 589824 = 4 * 147456 threads
    {
        int flat = (((b * 9 + k) << 4) + blockIdx.x) * 256 + tid;
        #pragma unroll
        for (int j = 0; j < 4; j++) {
            int i = flat + j * 147456;
            g_wh[i] = __float2half_rn(weight[i]);
        }
    }

    const int kh = k / 3, kw = k - kh * 3;
    const float* offb = offset + (b * 18 + 2 * k) * P_;
    const float* mb   = mask + (b * 9 + k) * P_;

    int   idx[2][4];
    float wgt[2][4];
    #pragma unroll
    for (int pi = 0; pi < 2; pi++) {
        int p = p0 + pi;
        int oy = p >> 6, ox = p & 63;
        float dy = offb[p];
        float dx = offb[P_ + p];
        float m  = mb[p];

        float sy = (float)(oy - 1 + kh) + dy;
        float sx = (float)(ox - 1 + kw) + dx;
        float y0f = floorf(sy), x0f = floorf(sx);
        float wy = sy - y0f,    wx = sx - x0f;
        int y0 = (int)y0f, x0 = (int)x0f;
        int y1 = y0 + 1,   x1 = x0 + 1;

        bool vy0 = ((unsigned)y0 < 64u), vy1 = ((unsigned)y1 < 64u);
        bool vx0 = ((unsigned)x0 < 64u), vx1 = ((unsigned)x1 < 64u);
        int cy0 = min(max(y0, 0), 63), cy1 = min(max(y1, 0), 63);
        int cx0 = min(max(x0, 0), 63), cx1 = min(max(x1, 0), 63);
        idx[pi][0] = cy0 * 64 + cx0; idx[pi][1] = cy0 * 64 + cx1;
        idx[pi][2] = cy1 * 64 + cx0; idx[pi][3] = cy1 * 64 + cx1;

        float w00 = (1.f - wy) * (1.f - wx) * m; if (!(vy0 && vx0)) w00 = 0.f;
        float w01 = (1.f - wy) * wx * m;         if (!(vy0 && vx1)) w01 = 0.f;
        float w10 = wy * (1.f - wx) * m;         if (!(vy1 && vx0)) w10 = 0.f;
        float w11 = wy * wx * m;                 if (!(vy1 && vx1)) w11 = 0.f;
        wgt[pi][0] = w00; wgt[pi][1] = w01; wgt[pi][2] = w10; wgt[pi][3] = w11;
    }

    const int c0 = chalf * 128;
    const float* xb = x + b * (CIN_ * P_) + c0 * P_;
    const size_t nbase = (size_t)b * P_ + p0;

    #pragma unroll 2
    for (int ci = 0; ci < 128; ci++) {
        const float* xp = xb + ci * P_;
        float v0 = wgt[0][0] * __ldg(xp + idx[0][0])
                 + wgt[0][1] * __ldg(xp + idx[0][1])
                 + wgt[0][2] * __ldg(xp + idx[0][2])
                 + wgt[0][3] * __ldg(xp + idx[0][3]);
        float v1 = wgt[1][0] * __ldg(xp + idx[1][0])
                 + wgt[1][1] * __ldg(xp + idx[1][1])
                 + wgt[1][2] * __ldg(xp + idx[1][2])
                 + wgt[1][3] * __ldg(xp + idx[1][3]);
        size_t off = (size_t)((c0 + ci) * 9 + k) * NTOT + nbase;
        *(uint32_t*)(g_cols + off) =
            pk_h2(__float2half_rn(v0), __float2half_rn(v1));
    }
}

// ---------------------------------------------------------------------------
// Kernel 2: single-product fp16 GEMM via mma.sync (HMMA)
//   C[256 x 16384] = W[256 x 2304] * cols[2304 x 16384] + bias
//   CTA 128x128, K-chunk 64, 16 warps (4x4), warp tile 32x32, 4-stage cp.async
// ---------------------------------------------------------------------------
#define BK      64
#define NCH     (RDIM / BK)       // 36
#define A_STRIDE 144              // bytes per m-row (128 data + 16 pad)
#define B_STRIDE 272              // bytes per k-row (256 data + 16 pad)
#define OFF_A   0
#define OFF_B   (128 * A_STRIDE)              // 18432
#define STAGE_BYTES (OFF_B + 64 * B_STRIDE)   // 35840
#define SMEM_TOTAL (4 * STAGE_BYTES)          // 143360

__global__ __launch_bounds__(512, 1) void gemm_mma_kernel(
    const float* __restrict__ bias, float* __restrict__ out)
{
    extern __shared__ char smem[];
    const uint32_t sb0 = smem_u32(smem);
    const int tid = threadIdx.x;
    const int lane = tid & 31, wid = tid >> 5;
    const int warp_m = wid >> 2;          // 0..3  -> m offset *32
    const int warp_n = wid & 3;           // 0..3  -> n offset *32
    const int bm = blockIdx.y * 128;
    const int n0 = blockIdx.x * 128;

    const int lgrp = lane >> 3, lr = lane & 7;
    const int a_row   = ((lgrp & 1) << 3) + lr;
    const int a_chunk = lgrp >> 1;
    const int b_krow  = ((lgrp & 1) << 3) + lr;
    const int b_col   = (warp_n << 5) + ((lgrp >> 1) << 3);

    const __half* WH = g_wh + (size_t)bm * RDIM;

    // cp.async indexing: A 1024 CP16 (2/thread), B 1024 CP16 (2/thread)
    const int a_r = tid >> 2, a_h = tid & 3;   // A: 128 rows, 8x16B per row
    const int b_r = tid >> 3, b_c = tid & 7;   // B: 64 rows, 16x16B per row

    float d[2][4][4];
    #pragma unroll
    for (int i = 0; i < 2; i++)
        #pragma unroll
        for (int j = 0; j < 4; j++)
            #pragma unroll
            for (int q = 0; q < 4; q++) d[i][j][q] = 0.f;

    auto load_stage = [&](int ch) {
        const int kc0 = ch * BK;
        const uint32_t st = sb0 + (ch & 3) * STAGE_BYTES;
        #pragma unroll
        for (int q = 0; q < 2; q++) {
            int c16 = a_h + q * 4;
            uint32_t dsta = st + OFF_A + a_r * A_STRIDE + c16 * 16;
            CP16(dsta, WH + (size_t)a_r * RDIM + kc0 + c16 * 8);
        }
        #pragma unroll
        for (int q = 0; q < 2; q++) {
            int c16 = b_c + q * 8;
            uint32_t dstb = st + OFF_B + b_r * B_STRIDE + c16 * 16;
            CP16(dstb, g_cols + (size_t)(kc0 + b_r) * NTOT + n0 + c16 * 8);
        }
    };

    load_stage(0); CP_COMMIT();
    load_stage(1); CP_COMMIT();
    load_stage(2); CP_COMMIT();

    for (int ch = 0; ch < NCH; ch++) {
        CP_WAIT2();
        __syncthreads();
        if (ch + 3 < NCH) load_stage(ch + 3);
        CP_COMMIT();

        const uint32_t st = sb0 + (ch & 3) * STAGE_BYTES;
        const uint32_t aBase = st + OFF_A +
            (warp_m * 32 + a_row) * A_STRIDE + a_chunk * 16;
        const uint32_t bBase = st + OFF_B + b_krow * B_STRIDE + b_col * 2;

        #pragma unroll
        for (int s = 0; s < 4; s++) {
            uint32_t af[2][4], bf[2][4];
            #pragma unroll
            for (int i = 0; i < 2; i++) {
                uint32_t aa = aBase + i * (16 * A_STRIDE) + s * 32;
                LDMX4(af[i][0], af[i][1], af[i][2], af[i][3], aa);
            }
            #pragma unroll
            for (int g = 0; g < 2; g++) {
                uint32_t ba = bBase + s * (16 * B_STRIDE) + g * 32;
                LDMX4T(bf[g][0], bf[g][1], bf[g][2], bf[g][3], ba);
            }
            #pragma unroll
            for (int i = 0; i < 2; i++)
                #pragma unroll
                for (int g = 0; g < 2; g++)
                    #pragma unroll
                    for (int jn = 0; jn < 2; jn++)
                        MMA16816F(d[i][g * 2 + jn], af[i],
                                  bf[g][jn * 2], bf[g][jn * 2 + 1]);
        }
    }

    // ---- epilogue ----
    const int row0 = lane >> 2, col0 = (lane & 3) * 2;
    const int bb = n0 >> 12;
    const int pbase = (n0 & 4095) + warp_n * 32 + col0;
    #pragma unroll
    for (int i = 0; i < 2; i++) {
        int co = bm + warp_m * 32 + i * 16 + row0;
        float bi0 = __ldg(bias + co);
        float bi1 = __ldg(bias + co + 8);
        float* o0 = out + ((size_t)(bb * COUT_ + co)) * P_ + pbase;
        float* o1 = o0 + 8 * P_;
        #pragma unroll
        for (int j = 0; j < 4; j++) {
            float2 v0 = make_float2(d[i][j][0] + bi0, d[i][j][1] + bi0);
            float2 v1 = make_float2(d[i][j][2] + bi1, d[i][j][3] + bi1);
            *(float2*)(o0 + j * 8) = v0;
            *(float2*)(o1 + j * 8) = v1;
        }
    }
}

// ---------------------------------------------------------------------------
extern "C" void kernel_launch(void* const* d_in, const int* in_sizes, int n_in,
                              void* d_out, int out_size) {
    const float* x      = (const float*)d_in[0];
    const float* offset = (const float*)d_in[1];
    const float* mask   = (const float*)d_in[2];
    const float* weight = (const float*)d_in[3];
    const float* bias   = (const float*)d_in[4];
    float* out = (float*)d_out;

    cudaFuncSetAttribute(gemm_mma_kernel,
                         cudaFuncAttributeMaxDynamicSharedMemorySize, SMEM_TOTAL);

    im2col_kernel<<<dim3(16, K_, B_), 256>>>(x, offset, mask, weight);
    gemm_mma_kernel<<<dim3(NTOT / 128, COUT_ / 128), 512, SMEM_TOTAL>>>(bias, out);
}

// round 15
// speedup vs baseline: 1.8822x; 1.0964x over previous
#include <cuda_runtime.h>
#include <cuda_fp16.h>
#include <cstdint>

#define B_    4
#define CIN_  256
#define P_    4096
#define K_    9
#define RDIM  2304          // CIN*9
#define COUT_ 256
#define NTOT  16384         // B*P

// ---------------------------------------------------------------------------
// Device scratch (static — no cudaMalloc allowed)
// ---------------------------------------------------------------------------
__device__ __align__(128) __half g_cols[(size_t)RDIM * NTOT];  // fp16 cols [r][n]
__device__ __align__(128) __half g_wh[COUT_ * RDIM];           // fp16 weights

__device__ __forceinline__ uint32_t smem_u32(const void* p) {
    uint32_t a;
    asm("{ .reg .u64 t; cvta.to.shared.u64 t, %1; cvt.u32.u64 %0, t; }"
        : "=r"(a) : "l"(p));
    return a;
}

#define CP16(dst, src) \
    asm volatile("cp.async.cg.shared.global [%0], [%1], 16;" \
                 :: "r"(dst), "l"(src) : "memory")
#define CP_COMMIT() asm volatile("cp.async.commit_group;" ::: "memory")
#define CP_WAIT1()  asm volatile("cp.async.wait_group 1;" ::: "memory")

#define LDMX4(r0, r1, r2, r3, a) \
    asm volatile("ldmatrix.sync.aligned.m8n8.x4.shared.b16 {%0,%1,%2,%3}, [%4];" \
                 : "=r"(r0), "=r"(r1), "=r"(r2), "=r"(r3) : "r"(a))
#define LDMX4T(r0, r1, r2, r3, a) \
    asm volatile("ldmatrix.sync.aligned.m8n8.x4.trans.shared.b16 {%0,%1,%2,%3}, [%4];" \
                 : "=r"(r0), "=r"(r1), "=r"(r2), "=r"(r3) : "r"(a))

#define MMA16816F(d, a, b0, b1) \
    asm volatile("mma.sync.aligned.m16n8k16.row.col.f32.f16.f16.f32 " \
                 "{%0,%1,%2,%3},{%4,%5,%6,%7},{%8,%9},{%0,%1,%2,%3};" \
                 : "+f"((d)[0]), "+f"((d)[1]), "+f"((d)[2]), "+f"((d)[3]) \
                 : "r"((a)[0]), "r"((a)[1]), "r"((a)[2]), "r"((a)[3]), \
                   "r"(b0), "r"(b1))

__device__ __forceinline__ uint32_t pk_h2(__half a, __half b) {
    return (uint32_t)__half_as_ushort(a) | ((uint32_t)__half_as_ushort(b) << 16);
}

// ---------------------------------------------------------------------------
// Kernel 1: weight fp16 convert (folded) + fused sampling + im2col -> fp16
//   2 p's per thread, channel loop split across 2 blocks.  (R14 config)
// ---------------------------------------------------------------------------
__global__ __launch_bounds__(256) void im2col_kernel(
    const float* __restrict__ x,
    const float* __restrict__ offset,
    const float* __restrict__ mask,
    const float* __restrict__ weight)
{
    const int tid = threadIdx.x;
    const int k = blockIdx.y, b = blockIdx.z;
    const int pxb = blockIdx.x >> 1;
    const int chalf = blockIdx.x & 1;
    const int p0 = pxb * 512 + tid * 2;

    // ---- folded weight convert: 589824 = 4 * 147456 threads
    {
        int flat = (((b * 9 + k) << 4) + blockIdx.x) * 256 + tid;
        #pragma unroll
        for (int j = 0; j < 4; j++) {
            int i = flat + j * 147456;
            g_wh[i] = __float2half_rn(weight[i]);
        }
    }

    const int kh = k / 3, kw = k - kh * 3;
    const float* offb = offset + (b * 18 + 2 * k) * P_;
    const float* mb   = mask + (b * 9 + k) * P_;

    int   idx[2][4];
    float wgt[2][4];
    #pragma unroll
    for (int pi = 0; pi < 2; pi++) {
        int p = p0 + pi;
        int oy = p >> 6, ox = p & 63;
        float dy = offb[p];
        float dx = offb[P_ + p];
        float m  = mb[p];

        float sy = (float)(oy - 1 + kh) + dy;
        float sx = (float)(ox - 1 + kw) + dx;
        float y0f = floorf(sy), x0f = floorf(sx);
        float wy = sy - y0f,    wx = sx - x0f;
        int y0 = (int)y0f, x0 = (int)x0f;
        int y1 = y0 + 1,   x1 = x0 + 1;

        bool vy0 = ((unsigned)y0 < 64u), vy1 = ((unsigned)y1 < 64u);
        bool vx0 = ((unsigned)x0 < 64u), vx1 = ((unsigned)x1 < 64u);
        int cy0 = min(max(y0, 0), 63), cy1 = min(max(y1, 0), 63);
        int cx0 = min(max(x0, 0), 63), cx1 = min(max(x1, 0), 63);
        idx[pi][0] = cy0 * 64 + cx0; idx[pi][1] = cy0 * 64 + cx1;
        idx[pi][2] = cy1 * 64 + cx0; idx[pi][3] = cy1 * 64 + cx1;

        float w00 = (1.f - wy) * (1.f - wx) * m; if (!(vy0 && vx0)) w00 = 0.f;
        float w01 = (1.f - wy) * wx * m;         if (!(vy0 && vx1)) w01 = 0.f;
        float w10 = wy * (1.f - wx) * m;         if (!(vy1 && vx0)) w10 = 0.f;
        float w11 = wy * wx * m;                 if (!(vy1 && vx1)) w11 = 0.f;
        wgt[pi][0] = w00; wgt[pi][1] = w01; wgt[pi][2] = w10; wgt[pi][3] = w11;
    }

    const int c0 = chalf * 128;
    const float* xb = x + b * (CIN_ * P_) + c0 * P_;
    const size_t nbase = (size_t)b * P_ + p0;

    #pragma unroll 2
    for (int ci = 0; ci < 128; ci++) {
        const float* xp = xb + ci * P_;
        float v0 = wgt[0][0] * __ldg(xp + idx[0][0])
                 + wgt[0][1] * __ldg(xp + idx[0][1])
                 + wgt[0][2] * __ldg(xp + idx[0][2])
                 + wgt[0][3] * __ldg(xp + idx[0][3]);
        float v1 = wgt[1][0] * __ldg(xp + idx[1][0])
                 + wgt[1][1] * __ldg(xp + idx[1][1])
                 + wgt[1][2] * __ldg(xp + idx[1][2])
                 + wgt[1][3] * __ldg(xp + idx[1][3]);
        size_t off = (size_t)((c0 + ci) * 9 + k) * NTOT + nbase;
        *(uint32_t*)(g_cols + off) =
            pk_h2(__float2half_rn(v0), __float2half_rn(v1));
    }
}

// ---------------------------------------------------------------------------
// Kernel 2: single-product fp16 GEMM via mma.sync (HMMA)
//   CTA tile 128x256 (amortize per-chunk overhead), K-chunk 64,
//   16 warps (4x4), warp tile 32x64, 3-stage cp.async. Grid = 128 CTAs.
// ---------------------------------------------------------------------------
#define BK      64
#define NCH     (RDIM / BK)       // 36
#define BN      256
#define A_STRIDE 144              // bytes per m-row (128 data + 16 pad)
#define B_STRIDE 528              // bytes per k-row (512 data + 16 pad)
#define OFF_A   0
#define OFF_B   (128 * A_STRIDE)              // 18432
#define STAGE_BYTES (OFF_B + 64 * B_STRIDE)   // 52224
#define SMEM_TOTAL (3 * STAGE_BYTES)          // 156672

__global__ __launch_bounds__(512, 1) void gemm_mma_kernel(
    const float* __restrict__ bias, float* __restrict__ out)
{
    extern __shared__ char smem[];
    const uint32_t sb0 = smem_u32(smem);
    const int tid = threadIdx.x;
    const int lane = tid & 31, wid = tid >> 5;
    const int warp_m = wid >> 2;          // 0..3 -> m offset *32
    const int warp_n = wid & 3;           // 0..3 -> n offset *64
    const int bm = blockIdx.y * 128;
    const int n0 = blockIdx.x * BN;

    const int lgrp = lane >> 3, lr = lane & 7;
    const int a_row   = ((lgrp & 1) << 3) + lr;
    const int a_chunk = lgrp >> 1;
    const int b_krow  = ((lgrp & 1) << 3) + lr;
    const int b_col   = warp_n * 64 + ((lgrp >> 1) << 3);

    const __half* WH = g_wh + (size_t)bm * RDIM;

    // cp.async indexing: A 1024 CP16 (2/thread), B 2048 CP16 (4/thread)
    const int a_r = tid >> 2, a_h = tid & 3;   // A: 128 rows, 8x16B per row
    const int b_r = tid >> 3, b_c = tid & 7;   // B: 64 rows, 32x16B per row

    float d[2][8][4];
    #pragma unroll
    for (int i = 0; i < 2; i++)
        #pragma unroll
        for (int j = 0; j < 8; j++)
            #pragma unroll
            for (int q = 0; q < 4; q++) d[i][j][q] = 0.f;

    auto load_stage = [&](int ch) {
        const int kc0 = ch * BK;
        const uint32_t st = sb0 + (ch % 3) * STAGE_BYTES;
        #pragma unroll
        for (int q = 0; q < 2; q++) {
            int c16 = a_h + q * 4;
            uint32_t dsta = st + OFF_A + a_r * A_STRIDE + c16 * 16;
            CP16(dsta, WH + (size_t)a_r * RDIM + kc0 + c16 * 8);
        }
        #pragma unroll
        for (int q = 0; q < 4; q++) {
            int c16 = b_c + q * 8;                 // 0..31
            uint32_t dstb = st + OFF_B + b_r * B_STRIDE + c16 * 16;
            CP16(dstb, g_cols + (size_t)(kc0 + b_r) * NTOT + n0 + c16 * 8);
        }
    };

    load_stage(0); CP_COMMIT();
    load_stage(1); CP_COMMIT();

    for (int ch = 0; ch < NCH; ch++) {
        CP_WAIT1();
        __syncthreads();
        if (ch + 2 < NCH) load_stage(ch + 2);
        CP_COMMIT();

        const uint32_t st = sb0 + (ch % 3) * STAGE_BYTES;
        const uint32_t aBase = st + OFF_A +
            (warp_m * 32 + a_row) * A_STRIDE + a_chunk * 16;
        const uint32_t bBase = st + OFF_B + b_krow * B_STRIDE + b_col * 2;

        #pragma unroll
        for (int s = 0; s < 4; s++) {
            uint32_t af[2][4], bf[4][4];
            #pragma unroll
            for (int i = 0; i < 2; i++) {
                uint32_t aa = aBase + i * (16 * A_STRIDE) + s * 32;
                LDMX4(af[i][0], af[i][1], af[i][2], af[i][3], aa);
            }
            #pragma unroll
            for (int g = 0; g < 4; g++) {
                uint32_t ba = bBase + s * (16 * B_STRIDE) + g * 32;
                LDMX4T(bf[g][0], bf[g][1], bf[g][2], bf[g][3], ba);
            }
            #pragma unroll
            for (int i = 0; i < 2; i++)
                #pragma unroll
                for (int g = 0; g < 4; g++)
                    #pragma unroll
                    for (int jn = 0; jn < 2; jn++)
                        MMA16816F(d[i][g * 2 + jn], af[i],
                                  bf[g][jn * 2], bf[g][jn * 2 + 1]);
        }
    }

    // ---- epilogue ----
    const int row0 = lane >> 2, col0 = (lane & 3) * 2;
    const int bb = n0 >> 12;
    const int pbase = (n0 & 4095) + warp_n * 64 + col0;
    #pragma unroll
    for (int i = 0; i < 2; i++) {
        int co = bm + warp_m * 32 + i * 16 + row0;
        float bi0 = __ldg(bias + co);
        float bi1 = __ldg(bias + co + 8);
        float* o0 = out + ((size_t)(bb * COUT_ + co)) * P_ + pbase;
        float* o1 = o0 + 8 * P_;
        #pragma unroll
        for (int j = 0; j < 8; j++) {
            float2 v0 = make_float2(d[i][j][0] + bi0, d[i][j][1] + bi0);
            float2 v1 = make_float2(d[i][j][2] + bi1, d[i][j][3] + bi1);
            *(float2*)(o0 + j * 8) = v0;
            *(float2*)(o1 + j * 8) = v1;
        }
    }
}

// ---------------------------------------------------------------------------
extern "C" void kernel_launch(void* const* d_in, const int* in_sizes, int n_in,
                              void* d_out, int out_size) {
    const float* x      = (const float*)d_in[0];
    const float* offset = (const float*)d_in[1];
    const float* mask   = (const float*)d_in[2];
    const float* weight = (const float*)d_in[3];
    const float* bias   = (const float*)d_in[4];
    float* out = (float*)d_out;

    cudaFuncSetAttribute(gemm_mma_kernel,
                         cudaFuncAttributeMaxDynamicSharedMemorySize, SMEM_TOTAL);

    im2col_kernel<<<dim3(16, K_, B_), 256>>>(x, offset, mask, weight);
    gemm_mma_kernel<<<dim3(NTOT / BN, COUT_ / 128), 512, SMEM_TOTAL>>>(bias, out);
}

// round 16
// speedup vs baseline: 2.4305x; 1.2913x over previous
#include <cuda_runtime.h>
#include <cuda_fp16.h>
#include <cstdint>

#define B_    4
#define CIN_  256
#define P_    4096
#define K_    9
#define RDIM  2304          // CIN*9
#define COUT_ 256
#define NTOT  16384         // B*P
#define XTOT  (B_ * CIN_ * P_)   // 4,194,304 elements

// ---------------------------------------------------------------------------
// Device scratch (static — no cudaMalloc allowed)
// ---------------------------------------------------------------------------
__device__ __align__(128) __half g_cols[(size_t)RDIM * NTOT];  // fp16 cols [r][n]
__device__ __align__(128) __half g_wh[COUT_ * RDIM];           // fp16 weights
// fp16 copies of x, packed as u32 pairs:
//   g_xh [j] = (x[2j],   x[2j+1])   (even-start pairs)
//   g_xhs[j] = (x[2j+1], x[2j+2])   (odd-start pairs)
__device__ __align__(128) uint32_t g_xh [XTOT / 2];
__device__ __align__(128) uint32_t g_xhs[XTOT / 2];

__device__ __forceinline__ uint32_t smem_u32(const void* p) {
    uint32_t a;
    asm("{ .reg .u64 t; cvta.to.shared.u64 t, %1; cvt.u32.u64 %0, t; }"
        : "=r"(a) : "l"(p));
    return a;
}

#define CP16(dst, src) \
    asm volatile("cp.async.cg.shared.global [%0], [%1], 16;" \
                 :: "r"(dst), "l"(src) : "memory")
#define CP_COMMIT() asm volatile("cp.async.commit_group;" ::: "memory")
#define CP_WAIT1()  asm volatile("cp.async.wait_group 1;" ::: "memory")

#define LDMX4(r0, r1, r2, r3, a) \
    asm volatile("ldmatrix.sync.aligned.m8n8.x4.shared.b16 {%0,%1,%2,%3}, [%4];" \
                 : "=r"(r0), "=r"(r1), "=r"(r2), "=r"(r3) : "r"(a))
#define LDMX4T(r0, r1, r2, r3, a) \
    asm volatile("ldmatrix.sync.aligned.m8n8.x4.trans.shared.b16 {%0,%1,%2,%3}, [%4];" \
                 : "=r"(r0), "=r"(r1), "=r"(r2), "=r"(r3) : "r"(a))

#define MMA16816F(d, a, b0, b1) \
    asm volatile("mma.sync.aligned.m16n8k16.row.col.f32.f16.f16.f32 " \
                 "{%0,%1,%2,%3},{%4,%5,%6,%7},{%8,%9},{%0,%1,%2,%3};" \
                 : "+f"((d)[0]), "+f"((d)[1]), "+f"((d)[2]), "+f"((d)[3]) \
                 : "r"((a)[0]), "r"((a)[1]), "r"((a)[2]), "r"((a)[3]), \
                   "r"(b0), "r"(b1))

__device__ __forceinline__ uint32_t pk_h2(__half a, __half b) {
    return (uint32_t)__half_as_ushort(a) | ((uint32_t)__half_as_ushort(b) << 16);
}

// ---------------------------------------------------------------------------
// Kernel 0: build fp16 paired copies of x  +  fp16 weight convert
//   1,048,576 threads, 4 x-elements each.
// ---------------------------------------------------------------------------
__global__ __launch_bounds__(256) void prep_kernel(
    const float* __restrict__ x, const float* __restrict__ weight)
{
    const size_t t = (size_t)blockIdx.x * 256 + threadIdx.x;   // < 1,048,576
    const size_t e = t * 4;
    float4 f = *(const float4*)(x + e);
    float e4 = (e + 4 < XTOT) ? __ldg(x + e + 4) : f.w;

    __half hx = __float2half_rn(f.x), hy = __float2half_rn(f.y);
    __half hz = __float2half_rn(f.z), hw = __float2half_rn(f.w);
    __half h4 = __float2half_rn(e4);

    *(uint2*)(g_xh  + 2 * t) = make_uint2(pk_h2(hx, hy), pk_h2(hz, hw));
    *(uint2*)(g_xhs + 2 * t) = make_uint2(pk_h2(hy, hz), pk_h2(hw, h4));

    // weight convert: 589,824 = 4 * 147,456
    if (t < 147456) {
        float4 w = *(const float4*)(weight + 4 * t);
        g_wh[4 * t + 0] = __float2half_rn(w.x);
        g_wh[4 * t + 1] = __float2half_rn(w.y);
        g_wh[4 * t + 2] = __float2half_rn(w.z);
        g_wh[4 * t + 3] = __float2half_rn(w.w);
    }
}

// ---------------------------------------------------------------------------
// Kernel 1: fused sampling + im2col -> fp16 cols, fp16 paired gathers.
//   2 p's per thread, channel loop split across 2 blocks.
//   grid (16, 9, 4) = 576 blocks x 256 threads.
// ---------------------------------------------------------------------------
__global__ __launch_bounds__(256) void im2col_kernel(
    const float* __restrict__ offset,
    const float* __restrict__ mask)
{
    const int tid = threadIdx.x;
    const int k = blockIdx.y, b = blockIdx.z;
    const int pxb = blockIdx.x >> 1;
    const int chalf = blockIdx.x & 1;
    const int p0 = pxb * 512 + tid * 2;
    const int c0 = chalf * 128;

    const int kh = k / 3, kw = k - kh * 3;
    const float* offb = offset + (b * 18 + 2 * k) * P_;
    const float* mb   = mask + (b * 9 + k) * P_;

    const uint32_t* ptr[2][2];    // [pi][row]
    float wgt[2][4];              // [pi][wA_r0, wB_r0, wA_r1, wB_r1]

    #pragma unroll
    for (int pi = 0; pi < 2; pi++) {
        int p = p0 + pi;
        int oy = p >> 6, ox = p & 63;
        float dy = offb[p];
        float dx = offb[P_ + p];
        float m  = mb[p];

        float sy = (float)(oy - 1 + kh) + dy;
        float sx = (float)(ox - 1 + kw) + dx;
        float y0f = floorf(sy), x0f = floorf(sx);
        float wy = sy - y0f,    wx = sx - x0f;
        int y0 = (int)y0f, x0 = (int)x0f;
        int y1 = y0 + 1,   x1 = x0 + 1;

        bool vy0 = ((unsigned)y0 < 64u), vy1 = ((unsigned)y1 < 64u);
        bool vx0 = ((unsigned)x0 < 64u), vx1 = ((unsigned)x1 < 64u);
        int cy0 = min(max(y0, 0), 63), cy1 = min(max(y1, 0), 63);
        int cx0 = min(max(x0, 0), 63), cx1 = min(max(x1, 0), 63);
        int cxb = min(max(x0, 0), 62);

        float w00 = (1.f - wy) * (1.f - wx) * m; if (!(vy0 && vx0)) w00 = 0.f;
        float w01 = (1.f - wy) * wx * m;         if (!(vy0 && vx1)) w01 = 0.f;
        float w10 = wy * (1.f - wx) * m;         if (!(vy1 && vx0)) w10 = 0.f;
        float w11 = wy * wx * m;                 if (!(vy1 && vx1)) w11 = 0.f;

        // fold corner weights onto the packed element pair (cxb, cxb+1)
        bool e00 = (cx0 == cxb);     // corner x0's element is pair-low?
        bool e10 = (cx1 == cxb);     // corner x1's element is pair-low?
        wgt[pi][0] = (e00 ? w00 : 0.f) + (e10 ? w01 : 0.f);   // wA row0
        wgt[pi][1] = (e00 ? 0.f : w00) + (e10 ? 0.f : w01);   // wB row0
        wgt[pi][2] = (e00 ? w10 : 0.f) + (e10 ? w11 : 0.f);   // wA row1
        wgt[pi][3] = (e00 ? 0.f : w10) + (e10 ? 0.f : w11);   // wB row1

        const uint32_t* base = ((cxb & 1) ? g_xhs : g_xh)
                             + ((size_t)(b * CIN_ + c0) << 11);   // *2048
        int j = cxb >> 1;
        ptr[pi][0] = base + cy0 * 32 + j;
        ptr[pi][1] = base + cy1 * 32 + j;
    }

    const size_t nbase = (size_t)b * P_ + p0;
    const uint32_t* p00 = ptr[0][0];
    const uint32_t* p01 = ptr[0][1];
    const uint32_t* p10 = ptr[1][0];
    const uint32_t* p11 = ptr[1][1];

    #pragma unroll 4
    for (int ci = 0; ci < 128; ci++) {
        uint32_t a00 = __ldg(p00), a01 = __ldg(p01);
        uint32_t a10 = __ldg(p10), a11 = __ldg(p11);
        float2 f00 = __half22float2(*reinterpret_cast<const __half2*>(&a00));
        float2 f01 = __half22float2(*reinterpret_cast<const __half2*>(&a01));
        float2 f10 = __half22float2(*reinterpret_cast<const __half2*>(&a10));
        float2 f11 = __half22float2(*reinterpret_cast<const __half2*>(&a11));

        float v0 = wgt[0][0] * f00.x + wgt[0][1] * f00.y
                 + wgt[0][2] * f01.x + wgt[0][3] * f01.y;
        float v1 = wgt[1][0] * f10.x + wgt[1][1] * f10.y
                 + wgt[1][2] * f11.x + wgt[1][3] * f11.y;

        size_t off = (size_t)((c0 + ci) * 9 + k) * NTOT + nbase;
        *(uint32_t*)(g_cols + off) =
            pk_h2(__float2half_rn(v0), __float2half_rn(v1));

        p00 += 2048; p01 += 2048; p10 += 2048; p11 += 2048;
    }
}

// ---------------------------------------------------------------------------
// Kernel 2: single-product fp16 GEMM via mma.sync (HMMA) — R15 config
//   CTA tile 128x256, K-chunk 64, 16 warps, warp tile 32x64, 3-stage cp.async
// ---------------------------------------------------------------------------
#define BK      64
#define NCH     (RDIM / BK)       // 36
#define BN      256
#define A_STRIDE 144
#define B_STRIDE 528
#define OFF_A   0
#define OFF_B   (128 * A_STRIDE)              // 18432
#define STAGE_BYTES (OFF_B + 64 * B_STRIDE)   // 52224
#define SMEM_TOTAL (3 * STAGE_BYTES)          // 156672

__global__ __launch_bounds__(512, 1) void gemm_mma_kernel(
    const float* __restrict__ bias, float* __restrict__ out)
{
    extern __shared__ char smem[];
    const uint32_t sb0 = smem_u32(smem);
    const int tid = threadIdx.x;
    const int lane = tid & 31, wid = tid >> 5;
    const int warp_m = wid >> 2;
    const int warp_n = wid & 3;
    const int bm = blockIdx.y * 128;
    const int n0 = blockIdx.x * BN;

    const int lgrp = lane >> 3, lr = lane & 7;
    const int a_row   = ((lgrp & 1) << 3) + lr;
    const int a_chunk = lgrp >> 1;
    const int b_krow  = ((lgrp & 1) << 3) + lr;
    const int b_col   = warp_n * 64 + ((lgrp >> 1) << 3);

    const __half* WH = g_wh + (size_t)bm * RDIM;

    const int a_r = tid >> 2, a_h = tid & 3;
    const int b_r = tid >> 3, b_c = tid & 7;

    float d[2][8][4];
    #pragma unroll
    for (int i = 0; i < 2; i++)
        #pragma unroll
        for (int j = 0; j < 8; j++)
            #pragma unroll
            for (int q = 0; q < 4; q++) d[i][j][q] = 0.f;

    auto load_stage = [&](int ch) {
        const int kc0 = ch * BK;
        const uint32_t st = sb0 + (ch % 3) * STAGE_BYTES;
        #pragma unroll
        for (int q = 0; q < 2; q++) {
            int c16 = a_h + q * 4;
            uint32_t dsta = st + OFF_A + a_r * A_STRIDE + c16 * 16;
            CP16(dsta, WH + (size_t)a_r * RDIM + kc0 + c16 * 8);
        }
        #pragma unroll
        for (int q = 0; q < 4; q++) {
            int c16 = b_c + q * 8;
            uint32_t dstb = st + OFF_B + b_r * B_STRIDE + c16 * 16;
            CP16(dstb, g_cols + (size_t)(kc0 + b_r) * NTOT + n0 + c16 * 8);
        }
    };

    load_stage(0); CP_COMMIT();
    load_stage(1); CP_COMMIT();

    for (int ch = 0; ch < NCH; ch++) {
        CP_WAIT1();
        __syncthreads();
        if (ch + 2 < NCH) load_stage(ch + 2);
        CP_COMMIT();

        const uint32_t st = sb0 + (ch % 3) * STAGE_BYTES;
        const uint32_t aBase = st + OFF_A +
            (warp_m * 32 + a_row) * A_STRIDE + a_chunk * 16;
        const uint32_t bBase = st + OFF_B + b_krow * B_STRIDE + b_col * 2;

        #pragma unroll
        for (int s = 0; s < 4; s++) {
            uint32_t af[2][4], bf[4][4];
            #pragma unroll
            for (int i = 0; i < 2; i++) {
                uint32_t aa = aBase + i * (16 * A_STRIDE) + s * 32;
                LDMX4(af[i][0], af[i][1], af[i][2], af[i][3], aa);
            }
            #pragma unroll
            for (int g = 0; g < 4; g++) {
                uint32_t ba = bBase + s * (16 * B_STRIDE) + g * 32;
                LDMX4T(bf[g][0], bf[g][1], bf[g][2], bf[g][3], ba);
            }
            #pragma unroll
            for (int i = 0; i < 2; i++)
                #pragma unroll
                for (int g = 0; g < 4; g++)
                    #pragma unroll
                    for (int jn = 0; jn < 2; jn++)
                        MMA16816F(d[i][g * 2 + jn], af[i],
                                  bf[g][jn * 2], bf[g][jn * 2 + 1]);
        }
    }

    // ---- epilogue ----
    const int row0 = lane >> 2, col0 = (lane & 3) * 2;
    const int bb = n0 >> 12;
    const int pbase = (n0 & 4095) + warp_n * 64 + col0;
    #pragma unroll
    for (int i = 0; i < 2; i++) {
        int co = bm + warp_m * 32 + i * 16 + row0;
        float bi0 = __ldg(bias + co);
        float bi1 = __ldg(bias + co + 8);
        float* o0 = out + ((size_t)(bb * COUT_ + co)) * P_ + pbase;
        float* o1 = o0 + 8 * P_;
        #pragma unroll
        for (int j = 0; j < 8; j++) {
            float2 v0 = make_float2(d[i][j][0] + bi0, d[i][j][1] + bi0);
            float2 v1 = make_float2(d[i][j][2] + bi1, d[i][j][3] + bi1);
            *(float2*)(o0 + j * 8) = v0;
            *(float2*)(o1 + j * 8) = v1;
        }
    }
}

// ---------------------------------------------------------------------------
extern "C" void kernel_launch(void* const* d_in, const int* in_sizes, int n_in,
                              void* d_out, int out_size) {
    const float* x      = (const float*)d_in[0];
    const float* offset = (const float*)d_in[1];
    const float* mask   = (const float*)d_in[2];
    const float* weight = (const float*)d_in[3];
    const float* bias   = (const float*)d_in[4];
    float* out = (float*)d_out;

    cudaFuncSetAttribute(gemm_mma_kernel,
                         cudaFuncAttributeMaxDynamicSharedMemorySize, SMEM_TOTAL);

    prep_kernel<<<4096, 256>>>(x, weight);
    im2col_kernel<<<dim3(16, K_, B_), 256>>>(offset, mask);
    gemm_mma_kernel<<<dim3(NTOT / BN, COUT_ / 128), 512, SMEM_TOTAL>>>(bias, out);
}